// round 3
// baseline (speedup 1.0000x reference)
#include <cuda_runtime.h>
#include <cuda_bf16.h>
#include <cstdint>

// ---------------------------------------------------------------------------
// CustomBLIP: sigmoid( relu( bilinear(img_n, txt_n; Wp) + bp ) @ Wc^T + bc )
//   img_n = l2norm(image_embeds @ Wi^T + bi), txt_n = l2norm(text @ Wt^T + bt)
// Core: feats[b,k] = sum_ij (img[b,i]*txt[b,j]) * Wp[k, i*512+j]
//   -> GEMM C[256,512] = A[256,262144] x Wp^T, A generated on the fly.
// ---------------------------------------------------------------------------

#define B_SZ   256
#define M_DIM  512
#define KIJ    (512 * 512)          // 262144
#define BKC    32                   // K-chunk (ij) per iter
#define ITERS  (KIJ / BKC)          // 8192
#define BM     128
#define BN     128
#define SPLITS 18

#define BSTR   20                   // Wp smem row stride in u32 (32 bf16 + pad)
#define TSTR   260                  // txt smem row stride in u32 (256 + pad)

// smem layout (u32 units): Bs[2][BN*BSTR] | Ts[BM*TSTR] | img_s[2][128]
#define SM_BS_OFF   0
#define SM_TS_OFF   (2 * BN * BSTR)                 // 5120
#define SM_IMG_OFF  (SM_TS_OFF + BM * TSTR)         // 38400
#define SM_U32_TOT  (SM_IMG_OFF + 256)              // 38656
#define SM_BYTES    (SM_U32_TOT * 4)                // 154624

// -------------------------------- scratch ---------------------------------
__device__ float          g_pre[2 * B_SZ * M_DIM];
__device__ __nv_bfloat16  g_imgb[B_SZ * M_DIM];
__device__ __nv_bfloat16  g_txtb[B_SZ * M_DIM];
__device__ float          g_feats[B_SZ * M_DIM];

// -------------------------------- helpers ---------------------------------
__device__ __forceinline__ uint32_t u32_of(__nv_bfloat162 v) {
    return *reinterpret_cast<uint32_t*>(&v);
}
__device__ __forceinline__ __nv_bfloat162 bf2_of(uint32_t v) {
    return *reinterpret_cast<__nv_bfloat162*>(&v);
}
__device__ __forceinline__ uint32_t hmul2u(uint32_t a, uint32_t b) {
    __nv_bfloat162 r = __hmul2(bf2_of(a), bf2_of(b));
    return u32_of(r);
}
__device__ __forceinline__ uint32_t bpack(float lo, float hi) {
    __nv_bfloat162 h = __floats2bfloat162_rn(lo, hi);
    return u32_of(h);
}
__device__ __forceinline__ void mma16816(float* d, const uint32_t* a, const uint32_t* b) {
    asm volatile(
        "mma.sync.aligned.m16n8k16.row.col.f32.bf16.bf16.f32 "
        "{%0,%1,%2,%3}, {%4,%5,%6,%7}, {%8,%9}, {%0,%1,%2,%3};\n"
        : "+f"(d[0]), "+f"(d[1]), "+f"(d[2]), "+f"(d[3])
        : "r"(a[0]), "r"(a[1]), "r"(a[2]), "r"(a[3]), "r"(b[0]), "r"(b[1]));
}

// ----------------------- stage 1: mapping GEMM ------------------------------
// P[path][b,m] = X[b,:] . W[m,:] + bias[m]   (256x512x512, fp32)
__global__ __launch_bounds__(256) void map_gemm(const float* __restrict__ X,
                                                const float* __restrict__ W,
                                                const float* __restrict__ bias,
                                                int path) {
    __shared__ float Xs[32][33];
    __shared__ float Ws[32][33];
    int tid = threadIdx.x;
    int tx = tid & 31, ty = tid >> 5;
    int mt = blockIdx.x, bt = blockIdx.y;
    float acc[4] = {0.f, 0.f, 0.f, 0.f};
    for (int d0 = 0; d0 < 512; d0 += 32) {
#pragma unroll
        for (int q = 0; q < 4; ++q) {
            int idx = tid + 256 * q;
            int r = idx >> 5, c = idx & 31;
            Xs[r][c] = X[(bt * 32 + r) * 512 + d0 + c];
            Ws[r][c] = W[(mt * 32 + r) * 512 + d0 + c];
        }
        __syncthreads();
#pragma unroll
        for (int kk = 0; kk < 32; ++kk) {
            float w = Ws[tx][kk];
#pragma unroll
            for (int r = 0; r < 4; ++r) acc[r] += Xs[ty + 8 * r][kk] * w;
        }
        __syncthreads();
    }
    float bb = bias[mt * 32 + tx];
#pragma unroll
    for (int r = 0; r < 4; ++r)
        g_pre[path * (B_SZ * M_DIM) + (bt * 32 + ty + 8 * r) * 512 + mt * 32 + tx] =
            acc[r] + bb;
}

// ----------------- stage 2: L2 normalize + bf16 cast + zero feats -----------
__global__ __launch_bounds__(128) void norm_zero() {
    int bx = blockIdx.x;
    int path = bx >> 8;
    int row = bx & 255;
    int t = threadIdx.x;
    const float* src = g_pre + path * (B_SZ * M_DIM) + row * 512;
    float v[4];
    float ss = 0.f;
#pragma unroll
    for (int q = 0; q < 4; ++q) {
        v[q] = src[t + 128 * q];
        ss += v[q] * v[q];
    }
#pragma unroll
    for (int o = 16; o > 0; o >>= 1) ss += __shfl_xor_sync(0xffffffffu, ss, o);
    __shared__ float sred[4];
    if ((t & 31) == 0) sred[t >> 5] = ss;
    __syncthreads();
    float tot = sred[0] + sred[1] + sred[2] + sred[3];
    float sc = 1.f / fmaxf(sqrtf(tot), 1e-12f);
    __nv_bfloat16* dst = (path == 0 ? g_imgb : g_txtb) + row * 512;
#pragma unroll
    for (int q = 0; q < 4; ++q) dst[t + 128 * q] = __float2bfloat16(v[q] * sc);
    if (path == 0) {
#pragma unroll
        for (int q = 0; q < 4; ++q) g_feats[row * 512 + t + 128 * q] = 0.f;
    }
}

// --------------------- stage 3: the big bilinear GEMM -----------------------
__global__ __launch_bounds__(256) void bilinear_gemm(const float* __restrict__ Wp) {
    extern __shared__ uint32_t smem[];
    uint32_t* Bs = smem + SM_BS_OFF;
    uint32_t* Ts = smem + SM_TS_OFF;
    uint32_t* img_s = smem + SM_IMG_OFF;

    int tid = threadIdx.x;
    int lane = tid & 31, warp = tid >> 5;
    int wm = warp >> 2, wn = warp & 3;   // 2 x 4 warp grid, warp tile 64x32
    int s = blockIdx.x, nt = blockIdx.y, mt = blockIdx.z;
    int b0 = mt * BM, k0 = nt * BN;

    // ---- txt cache: 128 rows x 512 bf16 (as 256 u32/row, padded stride) ----
    {
        const uint32_t* src = reinterpret_cast<const uint32_t*>(g_txtb) + b0 * 256;
        for (int idx = tid; idx < BM * 256; idx += 256) {
            int r = idx >> 8, c = idx & 255;
            Ts[r * TSTR + c] = src[idx];
        }
    }

    int kb = (int)(((long)ITERS * s) / SPLITS);
    int ke = (int)(((long)ITERS * (s + 1)) / SPLITS);

    float acc[4][4][4];
#pragma unroll
    for (int f = 0; f < 4; ++f)
#pragma unroll
        for (int g = 0; g < 4; ++g)
#pragma unroll
            for (int e = 0; e < 4; ++e) acc[f][g][e] = 0.f;

    // Wp staging assignment: thread -> (rows wr+32u, float4 seg wseg)
    int wr = tid >> 3, wseg = tid & 7;
    const float* wp_base = Wp + (size_t)k0 * KIJ;
    float4 wreg[4];

    int arow[8];
#pragma unroll
    for (int f = 0; f < 4; ++f) {
        arow[2 * f] = wm * 64 + f * 16 + (lane >> 2);
        arow[2 * f + 1] = arow[2 * f] + 8;
    }

    // ---- prologue: stage iter kb into buffer 0 ----
    {
        size_t ij0 = (size_t)kb * BKC;
#pragma unroll
        for (int u = 0; u < 4; ++u)
            wreg[u] = *reinterpret_cast<const float4*>(
                wp_base + (size_t)(wr + 32 * u) * KIJ + ij0 + wseg * 4);
#pragma unroll
        for (int u = 0; u < 4; ++u) {
            int r = wr + 32 * u;
            uint2 v;
            v.x = bpack(wreg[u].x, wreg[u].y);
            v.y = bpack(wreg[u].z, wreg[u].w);
            *reinterpret_cast<uint2*>(&Bs[0 * BN * BSTR + r * BSTR + wseg * 2]) = v;
        }
        if (tid < 128) {
            int i = (int)(ij0 >> 9);
            __nv_bfloat162 p = __bfloat162bfloat162(g_imgb[(b0 + tid) * 512 + i]);
            img_s[tid] = u32_of(p);
        }
    }
    __syncthreads();

#pragma unroll 1
    for (int it = kb; it < ke; ++it) {
        int p = (it - kb) & 1;
        bool pre = (it + 1 < ke);

        // ---- prefetch next iter (Wp tile + img column) into registers ----
        uint32_t inx = 0;
        if (pre) {
            size_t ij1 = (size_t)(it + 1) * BKC;
#pragma unroll
            for (int u = 0; u < 4; ++u)
                wreg[u] = *reinterpret_cast<const float4*>(
                    wp_base + (size_t)(wr + 32 * u) * KIJ + ij1 + wseg * 4);
            if (tid < 128) {
                int i = (int)(ij1 >> 9);
                __nv_bfloat162 pp = __bfloat162bfloat162(g_imgb[(b0 + tid) * 512 + i]);
                inx = u32_of(pp);
            }
        }

        // ---- compute current iter ----
        {
            int j0h = (int)((((size_t)it * BKC) & 511) >> 1);  // u32 offset of j0
            uint32_t im[8];
#pragma unroll
            for (int h = 0; h < 8; ++h) im[h] = img_s[p * 128 + arow[h]];
            const uint32_t* bs = Bs + p * BN * BSTR;
#pragma unroll
            for (int k2 = 0; k2 < 2; ++k2) {
                int co = j0h + k2 * 8 + (lane & 3);
                uint32_t a[4][4];
#pragma unroll
                for (int f = 0; f < 4; ++f) {
                    uint32_t t0 = Ts[arow[2 * f] * TSTR + co];
                    uint32_t t1 = Ts[arow[2 * f + 1] * TSTR + co];
                    uint32_t t2 = Ts[arow[2 * f] * TSTR + co + 4];
                    uint32_t t3 = Ts[arow[2 * f + 1] * TSTR + co + 4];
                    a[f][0] = hmul2u(t0, im[2 * f]);
                    a[f][1] = hmul2u(t1, im[2 * f + 1]);
                    a[f][2] = hmul2u(t2, im[2 * f]);
                    a[f][3] = hmul2u(t3, im[2 * f + 1]);
                }
                uint32_t bb[4][2];
#pragma unroll
                for (int g = 0; g < 4; ++g) {
                    int n = wn * 32 + g * 8 + (lane >> 2);
                    int base = n * BSTR + k2 * 8 + (lane & 3);
                    bb[g][0] = bs[base];
                    bb[g][1] = bs[base + 4];
                }
#pragma unroll
                for (int f = 0; f < 4; ++f)
#pragma unroll
                    for (int g = 0; g < 4; ++g) mma16816(acc[f][g], a[f], bb[g]);
            }
        }

        // ---- store prefetched data into the other buffer ----
        if (pre) {
#pragma unroll
            for (int u = 0; u < 4; ++u) {
                int r = wr + 32 * u;
                uint2 v;
                v.x = bpack(wreg[u].x, wreg[u].y);
                v.y = bpack(wreg[u].z, wreg[u].w);
                *reinterpret_cast<uint2*>(
                    &Bs[(p ^ 1) * BN * BSTR + r * BSTR + wseg * 2]) = v;
            }
            if (tid < 128) img_s[(p ^ 1) * 128 + tid] = inx;
        }
        __syncthreads();
    }

    // ---- split-K epilogue: accumulate partials into g_feats ----
#pragma unroll
    for (int f = 0; f < 4; ++f)
#pragma unroll
        for (int g = 0; g < 4; ++g)
#pragma unroll
            for (int e = 0; e < 4; ++e) {
                int rr = b0 + wm * 64 + f * 16 + (lane >> 2) + ((e >> 1) << 3);
                int cc = k0 + wn * 32 + g * 8 + ((lane & 3) << 1) + (e & 1);
                atomicAdd(&g_feats[rr * 512 + cc], acc[f][g][e]);
            }
}

// ------------------ stage 4: bias + relu + classifier + sigmoid -------------
__global__ __launch_bounds__(128) void final_k(const float* __restrict__ bp,
                                               const float* __restrict__ Wc,
                                               const float* __restrict__ bc,
                                               float* __restrict__ out) {
    int b = blockIdx.x;
    int t = threadIdx.x;
    float p = 0.f;
    for (int k = t; k < 512; k += 128) {
        float f = g_feats[b * 512 + k] + bp[k];
        f = fmaxf(f, 0.f);
        p += f * Wc[k];
    }
#pragma unroll
    for (int o = 16; o > 0; o >>= 1) p += __shfl_xor_sync(0xffffffffu, p, o);
    __shared__ float sr[4];
    if ((t & 31) == 0) sr[t >> 5] = p;
    __syncthreads();
    if (t == 0) {
        float logit = sr[0] + sr[1] + sr[2] + sr[3] + bc[0];
        out[b] = 1.f / (1.f + expf(-logit));
    }
}

// ------------------------------ launcher ------------------------------------
extern "C" void kernel_launch(void* const* d_in, const int* in_sizes, int n_in,
                              void* d_out, int out_size) {
    const float* img_e = (const float*)d_in[0];
    const float* txt_e = (const float*)d_in[1];
    const float* Wi = (const float*)d_in[2];
    const float* bi = (const float*)d_in[3];
    const float* Wt = (const float*)d_in[4];
    const float* bt = (const float*)d_in[5];
    const float* Wp = (const float*)d_in[6];
    const float* bp = (const float*)d_in[7];
    const float* Wc = (const float*)d_in[8];
    const float* bc = (const float*)d_in[9];
    float* out = (float*)d_out;

    cudaFuncSetAttribute(bilinear_gemm, cudaFuncAttributeMaxDynamicSharedMemorySize,
                         SM_BYTES);

    map_gemm<<<dim3(16, 8), 256>>>(img_e, Wi, bi, 0);
    map_gemm<<<dim3(16, 8), 256>>>(txt_e, Wt, bt, 1);
    norm_zero<<<512, 128>>>();
    bilinear_gemm<<<dim3(SPLITS, 4, 2), 256, SM_BYTES>>>(Wp);
    final_k<<<256, 128>>>(bp, Wc, bc, out);
}